// round 6
// baseline (speedup 1.0000x reference)
#include <cuda_runtime.h>
#include <math.h>

#define BB 16
#define TT 1024
#define NN 512
#define DD 512
#define INDIM 1536
#define EPSF 1e-8f

// ---------------- device scratch (no allocations allowed) ----------------
__device__ float g_xt  [BB*NN*TT];     // x transposed (B,N,T)
__device__ float g_rc  [BB*NN*TT];     // centered ranks (B,N,T)
__device__ float g_mu  [BB*NN];
__device__ float g_covP[BB*NN*NN];
__device__ float g_covS[BB*NN*NN];
__device__ float g_P   [BB*NN*NN];
__device__ float g_S   [BB*NN*NN];
__device__ float g_prec[BB*NN*NN];
__device__ float g_C   [BB*NN*NN];
__device__ float g_Af  [BB*NN*NN];
__device__ float g_An  [BB*NN*NN];
__device__ float g_X   [BB*NN*INDIM];
__device__ float g_Ybuf[BB*NN*DD];
__device__ float g_Hbuf[BB*NN*DD];
__device__ float g_stage[BB*NN*NN];    // GJ pivot-row staging
__device__ int   g_flags[BB*NN];       // GJ step flags
__device__ float g_sdP [BB*NN];
__device__ float g_sdS [BB*NN];
__device__ float g_sdQ [BB*NN];
__device__ float g_parts[BB*32*6];
__device__ float g_alph[BB*4];
__device__ float g_dinv[BB*NN];

__constant__ int c_BI[10] = {0,1,1,2,2,2,3,3,3,3};
__constant__ int c_BJ[10] = {0,0,1,0,1,2,0,1,2,3};

// ---------------- transpose x (B,T,N) -> xt (B,N,T) ----------------
__global__ void k_transpose(const float* __restrict__ x, float* __restrict__ xt) {
    __shared__ float tile[32][33];
    int b = blockIdx.z;
    int n0 = blockIdx.x * 32, t0 = blockIdx.y * 32;
    for (int r = threadIdx.y; r < 32; r += 8)
        tile[r][threadIdx.x] = x[((size_t)b*TT + t0 + r)*NN + n0 + threadIdx.x];
    __syncthreads();
    for (int r = threadIdx.y; r < 32; r += 8)
        xt[((size_t)b*NN + n0 + r)*TT + t0 + threadIdx.x] = tile[threadIdx.x][r];
}

// ---------------- per-column means ----------------
__global__ void k_mu(const float* __restrict__ xt, float* __restrict__ mu) {
    __shared__ float red[256];
    int bn = blockIdx.x;
    const float* row = xt + (size_t)bn*TT;
    float s = 0.f;
    for (int t = threadIdx.x; t < TT; t += 256) s += row[t];
    red[threadIdx.x] = s; __syncthreads();
    for (int o = 128; o > 0; o >>= 1) {
        if (threadIdx.x < o) red[threadIdx.x] += red[threadIdx.x + o];
        __syncthreads();
    }
    if (threadIdx.x == 0) mu[bn] = red[0] * (1.f / TT);
}

// ---------------- bitonic argsort -> centered ranks ----------------
__global__ __launch_bounds__(512) void k_sort(const float* __restrict__ xt, float* __restrict__ rc) {
    __shared__ unsigned long long keys[1024];
    int bn = blockIdx.x;
    const float* row = xt + (size_t)bn*TT;
    for (int t = threadIdx.x; t < 1024; t += 512) {
        unsigned u = __float_as_uint(row[t]);
        u = (u & 0x80000000u) ? ~u : (u | 0x80000000u);
        keys[t] = ((unsigned long long)u << 32) | (unsigned)t;
    }
    __syncthreads();
    for (int k2 = 2; k2 <= 1024; k2 <<= 1)
        for (int j = k2 >> 1; j > 0; j >>= 1) {
            int t = threadIdx.x;
            int i = ((t & ~(j-1)) << 1) | (t & (j-1));
            int l = i | j;
            unsigned long long a = keys[i], b2 = keys[l];
            if ((a > b2) == ((i & k2) == 0)) { keys[i] = b2; keys[l] = a; }
            __syncthreads();
        }
    float* out = rc + (size_t)bn*TT;
    for (int p = threadIdx.x; p < 1024; p += 512) {
        int idx = (int)(keys[p] & 0xffffffffu);
        out[idx] = (float)(p+1) - 512.5f;
    }
}

// ---------------- Gram (syrk, triangle blocks, optional mean-subtract) -----
__global__ __launch_bounds__(256) void k_gram(const float* __restrict__ A,
                                              const float* __restrict__ mu,
                                              float* __restrict__ Cout, float scale) {
    __shared__ float As[16][128];
    __shared__ float Bs[16][128];
    int p = blockIdx.x, b = blockIdx.y;
    int bi = c_BI[p], bj = c_BJ[p];
    int tid = threadIdx.x;
    int tx = tid & 15, ty = tid >> 4;
    const float* Ab = A + (size_t)b*NN*TT;
    const float* mub = mu ? (mu + b*NN) : (const float*)0;
    float acc[8][8];
#pragma unroll
    for (int i = 0; i < 8; ++i)
#pragma unroll
        for (int j = 0; j < 8; ++j) acc[i][j] = 0.f;

    for (int kt = 0; kt < TT; kt += 16) {
#pragma unroll
        for (int q = 0; q < 2; ++q) {
            int l = tid*2 + q;
            int row = l >> 2, t4 = (l & 3) * 4;
            {
                int gr = bi*128 + row;
                float4 v = *(const float4*)(Ab + (size_t)gr*TT + kt + t4);
                float m = mub ? mub[gr] : 0.f;
                As[t4+0][row] = v.x - m; As[t4+1][row] = v.y - m;
                As[t4+2][row] = v.z - m; As[t4+3][row] = v.w - m;
            }
            {
                int gr = bj*128 + row;
                float4 v = *(const float4*)(Ab + (size_t)gr*TT + kt + t4);
                float m = mub ? mub[gr] : 0.f;
                Bs[t4+0][row] = v.x - m; Bs[t4+1][row] = v.y - m;
                Bs[t4+2][row] = v.z - m; Bs[t4+3][row] = v.w - m;
            }
        }
        __syncthreads();
#pragma unroll
        for (int t = 0; t < 16; ++t) {
            float4 a0 = *(const float4*)&As[t][ty*8];
            float4 a1 = *(const float4*)&As[t][ty*8+4];
            float4 b0 = *(const float4*)&Bs[t][tx*8];
            float4 b1 = *(const float4*)&Bs[t][tx*8+4];
            float ar[8] = {a0.x,a0.y,a0.z,a0.w,a1.x,a1.y,a1.z,a1.w};
            float br[8] = {b0.x,b0.y,b0.z,b0.w,b1.x,b1.y,b1.z,b1.w};
#pragma unroll
            for (int i = 0; i < 8; ++i)
#pragma unroll
                for (int j = 0; j < 8; ++j) acc[i][j] += ar[i]*br[j];
        }
        __syncthreads();
    }
    float* Cb = Cout + (size_t)b*NN*NN;
#pragma unroll
    for (int i = 0; i < 8; ++i) {
        int gi = bi*128 + ty*8 + i;
#pragma unroll
        for (int j = 0; j < 8; ++j) {
            int gj = bj*128 + tx*8 + j;
            float v = acc[i][j] * scale;
            Cb[(size_t)gi*NN + gj] = v;
            if (bi != bj) Cb[(size_t)gj*NN + gi] = v;
        }
    }
}

// ---------------- diag std ----------------
__global__ void k_std(const float* __restrict__ cov, float* __restrict__ sd) {
    int e = blockIdx.x*blockDim.x + threadIdx.x;
    if (e >= BB*NN) return;
    int b = e >> 9, n = e & 511;
    sd[e] = sqrtf(fmaxf(cov[((size_t)b*NN + n)*NN + n], EPSF));
}

// ---------------- corr (cov -> corr, diag=1, nan->0) ----------------
__global__ void k_corr(const float* __restrict__ cov, const float* __restrict__ sd,
                       float* __restrict__ out) {
    for (int e = blockIdx.x*blockDim.x + threadIdx.x; e < BB*NN*NN; e += gridDim.x*blockDim.x) {
        int b = e >> 18, r = e & 262143, i = r >> 9, j = r & 511;
        float v;
        if (i == j) v = 1.f;
        else {
            v = cov[e] / (sd[b*NN+i]*sd[b*NN+j]);
            if (!isfinite(v)) v = 0.f;
        }
        out[e] = v;
    }
}

// ---------------- GJ flag reset ----------------
__global__ void k_zero() {
    int e = blockIdx.x*blockDim.x + threadIdx.x;
    if (e < BB*NN) g_flags[e] = 0;
}

// ---------------- distributed Gauss-Jordan SPD inverse ----------------
// 8 CTAs per batch, 64 rows each in smem; cross-CTA sync via L2 flags.
__global__ __launch_bounds__(256) void k_inv(const float* __restrict__ cov,
                                             float* __restrict__ prec) {
    extern __shared__ float a_s[];   // 64*512 floats
    int cta = blockIdx.x;
    int b = cta >> 3, rb = cta & 7, r0 = rb * 64;
    int tid = threadIdx.x;
    const float* src = cov + (size_t)b*NN*NN;
    for (int e = tid; e < 64*NN; e += 256) {
        int i = e >> 9, j = e & 511;
        float v = src[(size_t)(r0+i)*NN + j];
        if (r0 + i == j) v += 0.001f;
        a_s[e] = v;
    }
    float* stg = g_stage + (size_t)b*NN*NN;
    volatile int* flg = g_flags + b*NN;
    int col4 = tid & 127, rhalf = tid >> 7;
    __syncthreads();
    for (int k = 0; k < NN; ++k) {
        bool owner = (k >> 6) == rb;
        int kr = k - r0;
        if (owner) {
            float d = 1.0f / a_s[kr*NN + k];
            for (int q = tid; q < NN; q += 256) {
                float v = (q == k) ? d : a_s[kr*NN + q] * d;
                a_s[kr*NN + q] = v;
                stg[(size_t)k*NN + q] = v;
            }
            __syncthreads();
            __threadfence();
            if (tid == 0) flg[k] = 1;
        }
        if (tid == 0) { while (flg[k] == 0) { } }
        __syncthreads();
        float4 s4 = __ldcg((const float4*)(stg + (size_t)k*NN) + col4);
        int kc4 = k >> 2, kl = k & 3;
        float dpv = (kl==0) ? s4.x : (kl==1) ? s4.y : (kl==2) ? s4.z : s4.w;
#pragma unroll 4
        for (int ii = 0; ii < 32; ++ii) {
            int i = ii*2 + rhalf;
            if (owner && i == kr) continue;
            float f = a_s[i*NN + k];
            float4* r4 = (float4*)(a_s + i*NN);
            float4 v = r4[col4];
            v.x -= f*s4.x; v.y -= f*s4.y; v.z -= f*s4.z; v.w -= f*s4.w;
            if (col4 == kc4) {
                float nv = -f * dpv;
                if (kl==0) v.x = nv; else if (kl==1) v.y = nv;
                else if (kl==2) v.z = nv; else v.w = nv;
            }
            r4[col4] = v;
        }
        __syncthreads();
    }
    float* dst = prec + (size_t)b*NN*NN;
    for (int e = tid; e < 64*NN; e += 256)
        dst[(size_t)(r0 + (e>>9))*NN + (e & 511)] = a_s[e];
}

// ---------------- partial corr: tanh(-prec / sd sd), diag = tanh(1) -------
__global__ void k_pc(const float* __restrict__ prec, const float* __restrict__ sd,
                     float* __restrict__ out) {
    float t1 = tanhf(1.f);
    for (int e = blockIdx.x*blockDim.x + threadIdx.x; e < BB*NN*NN; e += gridDim.x*blockDim.x) {
        int b = e >> 18, r = e & 262143, i = r >> 9, j = r & 511;
        float v = (i == j) ? t1 : tanhf(-prec[e] / (sd[b*NN+i]*sd[b*NN+j]));
        out[e] = v;
    }
}

// ---------------- pairwise full-matrix dots (deterministic partials) ------
__global__ void k_dots(const float* __restrict__ P, const float* __restrict__ S,
                       const float* __restrict__ C, float* __restrict__ parts) {
    __shared__ float red[256];
    int b = blockIdx.y, ch = blockIdx.x;
    size_t base = (size_t)b*NN*NN + (size_t)ch*8192;
    float a[6] = {0,0,0,0,0,0};
    for (int e = threadIdx.x; e < 8192; e += 256) {
        float p = P[base+e], s = S[base+e], c = C[base+e];
        a[0] += p*p; a[1] += s*s; a[2] += c*c;
        a[3] += p*s; a[4] += p*c; a[5] += s*c;
    }
    for (int v = 0; v < 6; ++v) {
        red[threadIdx.x] = a[v]; __syncthreads();
        for (int o = 128; o > 0; o >>= 1) {
            if (threadIdx.x < o) red[threadIdx.x] += red[threadIdx.x + o];
            __syncthreads();
        }
        if (threadIdx.x == 0) parts[((size_t)b*32 + ch)*6 + v] = red[0];
        __syncthreads();
    }
}

// ---------------- sims + softmax alphas ----------------
__global__ void k_sims(const float* __restrict__ parts, const float* __restrict__ gamma,
                       float* __restrict__ alph) {
    int b = threadIdx.x;
    if (b >= BB) return;
    float F[6] = {0,0,0,0,0,0};
    for (int ch = 0; ch < 32; ++ch)
        for (int v = 0; v < 6; ++v) F[v] += parts[((size_t)b*32 + ch)*6 + v];
    float dC = tanhf(1.f);
    float dv[3] = {1.f, 1.f, dC};
    float D[3][3];
    D[0][0] = (F[0] - NN*dv[0]*dv[0]) * 0.5f;
    D[1][1] = (F[1] - NN*dv[1]*dv[1]) * 0.5f;
    D[2][2] = (F[2] - NN*dv[2]*dv[2]) * 0.5f;
    D[0][1] = D[1][0] = (F[3] - NN*dv[0]*dv[1]) * 0.5f;
    D[0][2] = D[2][0] = (F[4] - NN*dv[0]*dv[2]) * 0.5f;
    D[1][2] = D[2][1] = (F[5] - NN*dv[1]*dv[2]) * 0.5f;
    float rowsum[3], tot2 = 0.f;
    for (int v = 0; v < 3; ++v) {
        rowsum[v] = D[v][0] + D[v][1] + D[v][2];
        tot2 += rowsum[v];
    }
    float sims[3];
    for (int v = 0; v < 3; ++v) {
        float num = 0.5f * (rowsum[v] - D[v][v]);
        float nv = sqrtf(fmaxf(D[v][v], 0.f));
        float oo = 0.25f * (tot2 - 2.f*rowsum[v] + D[v][v]);
        float no = sqrtf(fmaxf(oo, 0.f));
        float den = fmaxf(nv, EPSF) * fmaxf(no, EPSF);
        sims[v] = num / den;
    }
    float g = gamma[0];
    float m = fmaxf(g*sims[0], fmaxf(g*sims[1], g*sims[2]));
    float e0 = expf(g*sims[0]-m), e1 = expf(g*sims[1]-m), e2 = expf(g*sims[2]-m);
    float si = 1.f / (e0 + e1 + e2);
    alph[b*4+0] = e0*si; alph[b*4+1] = e1*si; alph[b*4+2] = e2*si;
}

// ---------------- fuse (symmetrize C), diag=1 ----------------
__global__ void k_fuse(const float* __restrict__ P, const float* __restrict__ S,
                       const float* __restrict__ C, const float* __restrict__ alph,
                       float* __restrict__ Af) {
    for (int e = blockIdx.x*blockDim.x + threadIdx.x; e < BB*NN*NN; e += gridDim.x*blockDim.x) {
        int b = e >> 18, r = e & 262143, i = r >> 9, j = r & 511;
        float aP = alph[b*4+0], aS = alph[b*4+1], aC = alph[b*4+2];
        float ct = C[(size_t)b*NN*NN + (size_t)j*NN + i];
        float v = aP*P[e] + aS*S[e] + aC*0.5f*(C[e] + ct);
        if (i == j) v = 1.f;
        Af[e] = v;
    }
}

// ---------------- row sums -> d^-1/2 ----------------
__global__ void k_rowsum(const float* __restrict__ Af, float* __restrict__ dinv) {
    __shared__ float red[128];
    int bn = blockIdx.x;
    const float* row = Af + (size_t)bn*NN;
    float s = 0.f;
    for (int j = threadIdx.x; j < NN; j += 128) s += row[j];
    red[threadIdx.x] = s; __syncthreads();
    for (int o = 64; o > 0; o >>= 1) {
        if (threadIdx.x < o) red[threadIdx.x] += red[threadIdx.x + o];
        __syncthreads();
    }
    if (threadIdx.x == 0) dinv[bn] = rsqrtf(fmaxf(red[0], EPSF));
}

__global__ void k_norm(const float* __restrict__ Af, const float* __restrict__ dinv,
                       float* __restrict__ An) {
    for (int e = blockIdx.x*blockDim.x + threadIdx.x; e < BB*NN*NN; e += gridDim.x*blockDim.x) {
        int b = e >> 18, r = e & 262143, i = r >> 9, j = r & 511;
        An[e] = dinv[b*NN+i] * Af[e] * dinv[b*NN+j];
    }
}

// ---------------- layernorm over concat(P,S,C) row ----------------
__global__ __launch_bounds__(256) void k_ln(const float* __restrict__ P, const float* __restrict__ S,
                     const float* __restrict__ C, const float* __restrict__ lng,
                     const float* __restrict__ lnb, float* __restrict__ X) {
    __shared__ float red[256];
    int bn = blockIdx.x;
    float v[6];
#pragma unroll
    for (int q = 0; q < 6; ++q) {
        int c = threadIdx.x + q*256;
        int view = c >> 9, off = c & 511;
        const float* M = (view == 0) ? P : (view == 1) ? S : C;
        v[q] = M[(size_t)bn*NN + off];
    }
    float s = v[0]+v[1]+v[2]+v[3]+v[4]+v[5];
    red[threadIdx.x] = s; __syncthreads();
    for (int o = 128; o > 0; o >>= 1) {
        if (threadIdx.x < o) red[threadIdx.x] += red[threadIdx.x + o];
        __syncthreads();
    }
    float mean = red[0] * (1.f/INDIM);
    __syncthreads();
    float ss = 0.f;
#pragma unroll
    for (int q = 0; q < 6; ++q) { float d = v[q]-mean; ss += d*d; }
    red[threadIdx.x] = ss; __syncthreads();
    for (int o = 128; o > 0; o >>= 1) {
        if (threadIdx.x < o) red[threadIdx.x] += red[threadIdx.x + o];
        __syncthreads();
    }
    float inv = rsqrtf(red[0]*(1.f/INDIM) + 1e-5f);
#pragma unroll
    for (int q = 0; q < 6; ++q) {
        int c = threadIdx.x + q*256;
        X[(size_t)bn*INDIM + c] = (v[q]-mean)*inv*lng[c] + lnb[c];
    }
}

// ---------------- generic batched SGEMM: C = act(A@B + bias), Ncols=512 ---
__global__ __launch_bounds__(256) void k_mm(const float* __restrict__ A, long long sA,
                     const float* __restrict__ Bm, long long sB,
                     const float* __restrict__ bias,
                     float* __restrict__ Cm, long long sC, int K, int relu) {
    __shared__ float As[16][128];
    __shared__ float Bs[16][128];
    int bj = blockIdx.x, bi = blockIdx.y, b = blockIdx.z;
    int tid = threadIdx.x;
    int tx = tid & 15, ty = tid >> 4;
    const float* Ab = A + (size_t)b*sA;
    const float* Bb = Bm + (size_t)b*sB;
    float acc[8][8];
#pragma unroll
    for (int i = 0; i < 8; ++i)
#pragma unroll
        for (int j = 0; j < 8; ++j) acc[i][j] = 0.f;

    for (int kt = 0; kt < K; kt += 16) {
#pragma unroll
        for (int q = 0; q < 2; ++q) {
            int l = tid*2 + q;
            {
                int row = l >> 2, t4 = (l & 3) * 4;
                float4 v = *(const float4*)(Ab + (size_t)(bi*128+row)*K + kt + t4);
                As[t4+0][row] = v.x; As[t4+1][row] = v.y;
                As[t4+2][row] = v.z; As[t4+3][row] = v.w;
            }
            {
                int kr = l >> 5, n4 = (l & 31) * 4;
                float4 v = *(const float4*)(Bb + (size_t)(kt+kr)*NN + bj*128 + n4);
                *(float4*)&Bs[kr][n4] = v;
            }
        }
        __syncthreads();
#pragma unroll
        for (int t = 0; t < 16; ++t) {
            float4 a0 = *(const float4*)&As[t][ty*8];
            float4 a1 = *(const float4*)&As[t][ty*8+4];
            float4 b0 = *(const float4*)&Bs[t][tx*8];
            float4 b1 = *(const float4*)&Bs[t][tx*8+4];
            float ar[8] = {a0.x,a0.y,a0.z,a0.w,a1.x,a1.y,a1.z,a1.w};
            float br[8] = {b0.x,b0.y,b0.z,b0.w,b1.x,b1.y,b1.z,b1.w};
#pragma unroll
            for (int i = 0; i < 8; ++i)
#pragma unroll
                for (int j = 0; j < 8; ++j) acc[i][j] += ar[i]*br[j];
        }
        __syncthreads();
    }
    float* Cb = Cm + (size_t)b*sC;
#pragma unroll
    for (int i = 0; i < 8; ++i) {
        int gi = bi*128 + ty*8 + i;
#pragma unroll
        for (int j = 0; j < 8; ++j) {
            int gj = bj*128 + tx*8 + j;
            float v = acc[i][j] + (bias ? bias[gj] : 0.f);
            if (relu) v = fmaxf(v, 0.f);
            Cb[(size_t)gi*NN + gj] = v;
        }
    }
}

// ---------------- head: mean over nodes, dot Wc, sigmoid ----------------
__global__ void k_head(const float* __restrict__ H, const float* __restrict__ Wc,
                       const float* __restrict__ bc, float* __restrict__ out) {
    __shared__ float red[512];
    int b = blockIdx.x, d = threadIdx.x;
    float s = 0.f;
    for (int i = 0; i < NN; ++i) s += H[((size_t)b*NN + i)*DD + d];
    red[d] = (s * (1.f/NN)) * Wc[d];
    __syncthreads();
    for (int o = 256; o > 0; o >>= 1) {
        if (d < o) red[d] += red[d + o];
        __syncthreads();
    }
    if (d == 0) out[b] = 1.f / (1.f + expf(-(red[0] + bc[0])));
}

// ---------------- host ----------------
extern "C" void kernel_launch(void* const* d_in, const int* in_sizes, int n_in,
                              void* d_out, int out_size) {
    const float* x    = (const float*)d_in[0];
    const float* gam  = (const float*)d_in[1];
    const float* lng  = (const float*)d_in[2];
    const float* lnb  = (const float*)d_in[3];
    const float* W0   = (const float*)d_in[4];
    const float* b0   = (const float*)d_in[5];
    const float* W1   = (const float*)d_in[6];
    const float* b1   = (const float*)d_in[7];
    const float* W2   = (const float*)d_in[8];
    const float* b2   = (const float*)d_in[9];
    const float* Wc   = (const float*)d_in[10];
    const float* bc   = (const float*)d_in[11];
    float* out = (float*)d_out;

    float *pXt,*pRc,*pMu,*pCovP,*pCovS,*pP,*pS,*pPrec,*pC,*pAf,*pAn,*pX,*pY,*pH;
    float *pSdP,*pSdS,*pSdQ,*pParts,*pAl,*pDinv;
    cudaGetSymbolAddress((void**)&pXt,   g_xt);
    cudaGetSymbolAddress((void**)&pRc,   g_rc);
    cudaGetSymbolAddress((void**)&pMu,   g_mu);
    cudaGetSymbolAddress((void**)&pCovP, g_covP);
    cudaGetSymbolAddress((void**)&pCovS, g_covS);
    cudaGetSymbolAddress((void**)&pP,    g_P);
    cudaGetSymbolAddress((void**)&pS,    g_S);
    cudaGetSymbolAddress((void**)&pPrec, g_prec);
    cudaGetSymbolAddress((void**)&pC,    g_C);
    cudaGetSymbolAddress((void**)&pAf,   g_Af);
    cudaGetSymbolAddress((void**)&pAn,   g_An);
    cudaGetSymbolAddress((void**)&pX,    g_X);
    cudaGetSymbolAddress((void**)&pY,    g_Ybuf);
    cudaGetSymbolAddress((void**)&pH,    g_Hbuf);
    cudaGetSymbolAddress((void**)&pSdP,  g_sdP);
    cudaGetSymbolAddress((void**)&pSdS,  g_sdS);
    cudaGetSymbolAddress((void**)&pSdQ,  g_sdQ);
    cudaGetSymbolAddress((void**)&pParts,g_parts);
    cudaGetSymbolAddress((void**)&pAl,   g_alph);
    cudaGetSymbolAddress((void**)&pDinv, g_dinv);

    cudaFuncSetAttribute(k_inv, cudaFuncAttributeMaxDynamicSharedMemorySize, 64*NN*4);

    const float GSCALE = (float)(1.0 / (1023.0 + 1e-8));

    k_transpose<<<dim3(NN/32, TT/32, BB), dim3(32,8)>>>(x, pXt);
    k_mu<<<BB*NN, 256>>>(pXt, pMu);
    k_sort<<<BB*NN, 512>>>(pXt, pRc);

    k_gram<<<dim3(10, BB), 256>>>(pXt, pMu, pCovP, GSCALE);
    k_gram<<<dim3(10, BB), 256>>>(pRc, (const float*)0, pCovS, GSCALE);

    k_std<<<(BB*NN+255)/256, 256>>>(pCovP, pSdP);
    k_std<<<(BB*NN+255)/256, 256>>>(pCovS, pSdS);
    k_corr<<<8192, 256>>>(pCovP, pSdP, pP);
    k_corr<<<8192, 256>>>(pCovS, pSdS, pS);

    k_zero<<<32, 256>>>();
    k_inv<<<128, 256, 64*NN*4>>>(pCovP, pPrec);
    k_std<<<(BB*NN+255)/256, 256>>>(pPrec, pSdQ);
    k_pc<<<8192, 256>>>(pPrec, pSdQ, pC);

    k_dots<<<dim3(32, BB), 256>>>(pP, pS, pC, pParts);
    k_sims<<<1, 32>>>(pParts, gam, pAl);
    k_fuse<<<8192, 256>>>(pP, pS, pC, pAl, pAf);
    k_rowsum<<<BB*NN, 128>>>(pAf, pDinv);
    k_norm<<<8192, 256>>>(pAf, pDinv, pAn);
    k_ln<<<BB*NN, 256>>>(pP, pS, pC, lng, lnb, pX);

    long long sX = (long long)NN*INDIM, sM = (long long)NN*DD, sA2 = (long long)NN*NN;
    k_mm<<<dim3(4,4,BB), 256>>>(pX,  sX,  W0, 0LL, b0, pY, sM, INDIM, 0);
    k_mm<<<dim3(4,4,BB), 256>>>(pAn, sA2, pY, sM, (const float*)0, pH, sM, DD, 1);
    k_mm<<<dim3(4,4,BB), 256>>>(pH,  sM,  W1, 0LL, b1, pY, sM, DD, 0);
    k_mm<<<dim3(4,4,BB), 256>>>(pAn, sA2, pY, sM, (const float*)0, pH, sM, DD, 1);
    k_mm<<<dim3(4,4,BB), 256>>>(pH,  sM,  W2, 0LL, b2, pY, sM, DD, 0);
    k_mm<<<dim3(4,4,BB), 256>>>(pAn, sA2, pY, sM, (const float*)0, pH, sM, DD, 1);

    k_head<<<BB, 512>>>(pH, Wc, bc, out);

    (void)in_sizes; (void)n_in; (void)out_size;
}

// round 7
// speedup vs baseline: 1.4662x; 1.4662x over previous
#include <cuda_runtime.h>
#include <math.h>

#define BB 16
#define TT 1024
#define NN 512
#define DD 512
#define INDIM 1536
#define EPSF 1e-8f

// ---------------- device scratch (no allocations allowed) ----------------
__device__ float g_xt  [BB*NN*TT];     // x transposed (B,N,T)
__device__ float g_rc  [BB*NN*TT];     // centered ranks (B,N,T)
__device__ float g_mu  [BB*NN];
__device__ float g_covP[BB*NN*NN];
__device__ float g_covS[BB*NN*NN];
__device__ float g_P   [BB*NN*NN];
__device__ float g_S   [BB*NN*NN];
__device__ float g_prec[BB*NN*NN];
__device__ float g_C   [BB*NN*NN];
__device__ float g_Af  [BB*NN*NN];
__device__ float g_An  [BB*NN*NN];
__device__ float g_X   [BB*NN*INDIM];
__device__ float g_Ybuf[BB*NN*DD];
__device__ float g_Hbuf[BB*NN*DD];
__device__ float g_stage[BB*NN*NN];    // GJ pivot-panel staging / head partials
__device__ int   g_flags[BB*NN];       // GJ panel flags
__device__ float g_sdP [BB*NN];
__device__ float g_sdS [BB*NN];
__device__ float g_sdQ [BB*NN];
__device__ float g_parts[BB*32*6];
__device__ float g_alph[BB*4];
__device__ float g_dinv[BB*NN];

__constant__ int c_BI[10] = {0,1,1,2,2,2,3,3,3,3};
__constant__ int c_BJ[10] = {0,0,1,0,1,2,0,1,2,3};

// ---------------- transpose x (B,T,N) -> xt (B,N,T) ----------------
__global__ void k_transpose(const float* __restrict__ x, float* __restrict__ xt) {
    __shared__ float tile[32][33];
    int b = blockIdx.z;
    int n0 = blockIdx.x * 32, t0 = blockIdx.y * 32;
    for (int r = threadIdx.y; r < 32; r += 8)
        tile[r][threadIdx.x] = x[((size_t)b*TT + t0 + r)*NN + n0 + threadIdx.x];
    __syncthreads();
    for (int r = threadIdx.y; r < 32; r += 8)
        xt[((size_t)b*NN + n0 + r)*TT + t0 + threadIdx.x] = tile[threadIdx.x][r];
}

// ---------------- per-column means ----------------
__global__ void k_mu(const float* __restrict__ xt, float* __restrict__ mu) {
    __shared__ float red[256];
    int bn = blockIdx.x;
    const float* row = xt + (size_t)bn*TT;
    float s = 0.f;
    for (int t = threadIdx.x; t < TT; t += 256) s += row[t];
    red[threadIdx.x] = s; __syncthreads();
    for (int o = 128; o > 0; o >>= 1) {
        if (threadIdx.x < o) red[threadIdx.x] += red[threadIdx.x + o];
        __syncthreads();
    }
    if (threadIdx.x == 0) mu[bn] = red[0] * (1.f / TT);
}

// ---------------- bitonic argsort -> centered ranks ----------------
__global__ __launch_bounds__(512) void k_sort(const float* __restrict__ xt, float* __restrict__ rc) {
    __shared__ unsigned long long keys[1024];
    int bn = blockIdx.x;
    const float* row = xt + (size_t)bn*TT;
    for (int t = threadIdx.x; t < 1024; t += 512) {
        unsigned u = __float_as_uint(row[t]);
        u = (u & 0x80000000u) ? ~u : (u | 0x80000000u);
        keys[t] = ((unsigned long long)u << 32) | (unsigned)t;
    }
    __syncthreads();
    for (int k2 = 2; k2 <= 1024; k2 <<= 1)
        for (int j = k2 >> 1; j > 0; j >>= 1) {
            int t = threadIdx.x;
            int i = ((t & ~(j-1)) << 1) | (t & (j-1));
            int l = i | j;
            unsigned long long a = keys[i], b2 = keys[l];
            if ((a > b2) == ((i & k2) == 0)) { keys[i] = b2; keys[l] = a; }
            __syncthreads();
        }
    float* out = rc + (size_t)bn*TT;
    for (int p = threadIdx.x; p < 1024; p += 512) {
        int idx = (int)(keys[p] & 0xffffffffu);
        out[idx] = (float)(p+1) - 512.5f;
    }
}

// ---------------- merged Gram (Pearson z=0 / Spearman z=1), double-buffered
__global__ __launch_bounds__(256,2) void k_gram(const float* __restrict__ xt,
                                                const float* __restrict__ rc,
                                                const float* __restrict__ mu,
                                                float* __restrict__ covP,
                                                float* __restrict__ covS, float scale) {
    __shared__ float As[2][16][128];
    __shared__ float Bs[2][16][128];
    int p = blockIdx.x, b = blockIdx.y, z = blockIdx.z;
    int bi = c_BI[p], bj = c_BJ[p];
    int tid = threadIdx.x;
    int tx = tid & 15, ty = tid >> 4;
    const float* Ab = (z ? rc : xt) + (size_t)b*NN*TT;
    float* Cout = z ? covS : covP;

    int l0 = tid*2, l1 = tid*2 + 1;
    int rA0 = l0 >> 2, kA0 = (l0 & 3) * 4;
    int rA1 = l1 >> 2, kA1 = (l1 & 3) * 4;
    float mA0 = 0.f, mA1 = 0.f, mB0 = 0.f, mB1 = 0.f;
    if (!z) {
        const float* mub = mu + b*NN;
        mA0 = mub[bi*128+rA0]; mA1 = mub[bi*128+rA1];
        mB0 = mub[bj*128+rA0]; mB1 = mub[bj*128+rA1];
    }
    const float* A0 = Ab + (size_t)(bi*128+rA0)*TT + kA0;
    const float* A1 = Ab + (size_t)(bi*128+rA1)*TT + kA1;
    const float* B0 = Ab + (size_t)(bj*128+rA0)*TT + kA0;
    const float* B1 = Ab + (size_t)(bj*128+rA1)*TT + kA1;

    float acc[8][8];
#pragma unroll
    for (int i = 0; i < 8; ++i)
#pragma unroll
        for (int j = 0; j < 8; ++j) acc[i][j] = 0.f;

    float4 ra0 = *(const float4*)A0, ra1 = *(const float4*)A1;
    float4 rb0 = *(const float4*)B0, rb1 = *(const float4*)B1;
    As[0][kA0+0][rA0] = ra0.x - mA0; As[0][kA0+1][rA0] = ra0.y - mA0;
    As[0][kA0+2][rA0] = ra0.z - mA0; As[0][kA0+3][rA0] = ra0.w - mA0;
    As[0][kA1+0][rA1] = ra1.x - mA1; As[0][kA1+1][rA1] = ra1.y - mA1;
    As[0][kA1+2][rA1] = ra1.z - mA1; As[0][kA1+3][rA1] = ra1.w - mA1;
    Bs[0][kA0+0][rA0] = rb0.x - mB0; Bs[0][kA0+1][rA0] = rb0.y - mB0;
    Bs[0][kA0+2][rA0] = rb0.z - mB0; Bs[0][kA0+3][rA0] = rb0.w - mB0;
    Bs[0][kA1+0][rA1] = rb1.x - mB1; Bs[0][kA1+1][rA1] = rb1.y - mB1;
    Bs[0][kA1+2][rA1] = rb1.z - mB1; Bs[0][kA1+3][rA1] = rb1.w - mB1;
    __syncthreads();

    int buf = 0;
    for (int kt = 16; kt <= TT; kt += 16) {
        bool more = (kt < TT);
        if (more) {
            ra0 = *(const float4*)(A0 + kt); ra1 = *(const float4*)(A1 + kt);
            rb0 = *(const float4*)(B0 + kt); rb1 = *(const float4*)(B1 + kt);
        }
#pragma unroll
        for (int t = 0; t < 16; ++t) {
            float4 a0 = *(const float4*)&As[buf][t][ty*8];
            float4 a1 = *(const float4*)&As[buf][t][ty*8+4];
            float4 b0 = *(const float4*)&Bs[buf][t][tx*8];
            float4 b1 = *(const float4*)&Bs[buf][t][tx*8+4];
            float ar[8] = {a0.x,a0.y,a0.z,a0.w,a1.x,a1.y,a1.z,a1.w};
            float br[8] = {b0.x,b0.y,b0.z,b0.w,b1.x,b1.y,b1.z,b1.w};
#pragma unroll
            for (int i = 0; i < 8; ++i)
#pragma unroll
                for (int j = 0; j < 8; ++j) acc[i][j] += ar[i]*br[j];
        }
        if (more) {
            int nb = buf ^ 1;
            As[nb][kA0+0][rA0] = ra0.x - mA0; As[nb][kA0+1][rA0] = ra0.y - mA0;
            As[nb][kA0+2][rA0] = ra0.z - mA0; As[nb][kA0+3][rA0] = ra0.w - mA0;
            As[nb][kA1+0][rA1] = ra1.x - mA1; As[nb][kA1+1][rA1] = ra1.y - mA1;
            As[nb][kA1+2][rA1] = ra1.z - mA1; As[nb][kA1+3][rA1] = ra1.w - mA1;
            Bs[nb][kA0+0][rA0] = rb0.x - mB0; Bs[nb][kA0+1][rA0] = rb0.y - mB0;
            Bs[nb][kA0+2][rA0] = rb0.z - mB0; Bs[nb][kA0+3][rA0] = rb0.w - mB0;
            Bs[nb][kA1+0][rA1] = rb1.x - mB1; Bs[nb][kA1+1][rA1] = rb1.y - mB1;
            Bs[nb][kA1+2][rA1] = rb1.z - mB1; Bs[nb][kA1+3][rA1] = rb1.w - mB1;
            __syncthreads();
            buf = nb;
        }
    }
    float* Cb = Cout + (size_t)b*NN*NN;
#pragma unroll
    for (int i = 0; i < 8; ++i) {
        int gi = bi*128 + ty*8 + i;
#pragma unroll
        for (int j = 0; j < 8; ++j) {
            int gj = bj*128 + tx*8 + j;
            float v = acc[i][j] * scale;
            Cb[(size_t)gi*NN + gj] = v;
            if (bi != bj) Cb[(size_t)gj*NN + gi] = v;
        }
    }
}

// ---------------- diag std ----------------
__global__ void k_std(const float* __restrict__ cov, float* __restrict__ sd) {
    int e = blockIdx.x*blockDim.x + threadIdx.x;
    if (e >= BB*NN) return;
    int b = e >> 9, n = e & 511;
    sd[e] = sqrtf(fmaxf(cov[((size_t)b*NN + n)*NN + n], EPSF));
}

// ---------------- corr (both P and S in one pass) ----------------
__global__ void k_corr2(const float* __restrict__ covP, const float* __restrict__ sdP,
                        const float* __restrict__ covS, const float* __restrict__ sdS,
                        float* __restrict__ P, float* __restrict__ S) {
    for (int e = blockIdx.x*blockDim.x + threadIdx.x; e < BB*NN*NN; e += gridDim.x*blockDim.x) {
        int b = e >> 18, r = e & 262143, i = r >> 9, j = r & 511;
        float vp, vs;
        if (i == j) { vp = 1.f; vs = 1.f; }
        else {
            vp = covP[e] / (sdP[b*NN+i]*sdP[b*NN+j]);
            if (!isfinite(vp)) vp = 0.f;
            vs = covS[e] / (sdS[b*NN+i]*sdS[b*NN+j]);
            if (!isfinite(vs)) vs = 0.f;
        }
        P[e] = vp; S[e] = vs;
    }
}

// ---------------- GJ flag reset ----------------
__global__ void k_zero() {
    int e = blockIdx.x*blockDim.x + threadIdx.x;
    if (e < BB*NN) g_flags[e] = 0;
}

// ---------------- blocked distributed Gauss-Jordan SPD inverse ------------
// 8 CTAs per batch, 64 rows each resident in smem. 8 panels of 64 pivots.
// Per panel: owner inverts 64x64 diag block locally, publishes the fully
// reduced pivot rows P = [Binv | Binv@A_rest]; everyone else does a rank-64
// update A -= F @ P with panel columns pre-zeroed (giving -F@Binv there).
__global__ __launch_bounds__(256) void k_inv(const float* __restrict__ cov,
                                             float* __restrict__ prec) {
    extern __shared__ float sm[];
    float* a_s = sm;                          // 64*512
    float* w_s = sm + 64*512;                 // 64*65 (Binv for owner / F for others)
    float* p_s = sm + 64*512 + 64*65;         // 64*132 (panel-row chunk / fcol scratch)
    int cta = blockIdx.x;
    int b = cta >> 3, rb = cta & 7, r0 = rb * 64;
    int tid = threadIdx.x;
    int r = tid & 63, g = tid >> 6;           // GEMM layout: row r, col-group g
    const float* src = cov + (size_t)b*NN*NN;
    for (int e = tid; e < 64*NN; e += 256) {
        int i = e >> 9, j = e & 511;
        float v = src[(size_t)(r0+i)*NN + j];
        if (r0 + i == j) v += 0.001f;
        a_s[e] = v;
    }
    float* stg = g_stage + (size_t)b*NN*NN;
    volatile int* flg = g_flags + b*8;
    __syncthreads();

    for (int p = 0; p < 8; ++p) {
        int c0 = p * 64;
        if (rb == p) {
            // ---- local GJ on the 64x64 diagonal block -> w_s = Binv ----
            for (int e = tid; e < 64*64; e += 256)
                w_s[(e>>6)*65 + (e&63)] = a_s[(e>>6)*512 + c0 + (e&63)];
            __syncthreads();
            for (int k = 0; k < 64; ++k) {
                float d = 1.0f / w_s[k*65+k];
                __syncthreads();
                if (tid < 64)
                    w_s[k*65+tid] = (tid == k) ? d : w_s[k*65+tid] * d;
                else if (tid < 128)
                    p_s[tid-64] = w_s[(tid-64)*65 + k];   // multipliers f_i
                __syncthreads();
                for (int e = tid; e < 64*64; e += 256) {
                    int i = e >> 6, j = e & 63;
                    if (i == k) continue;
                    float f = p_s[i];
                    w_s[i*65+j] = (j == k) ? (-f*d) : (w_s[i*65+j] - f*w_s[k*65+j]);
                }
                __syncthreads();
            }
            // ---- P = Binv @ A_own ; panel cols <- Binv ; write stage + a_s ----
            for (int ch = 0; ch < 4; ++ch) {
                float4 acc[8];
#pragma unroll
                for (int q = 0; q < 8; ++q) acc[q] = make_float4(0.f,0.f,0.f,0.f);
                for (int k = 0; k < 64; ++k) {
                    float f = w_s[r*65+k];
                    const float4* arow = (const float4*)(a_s + k*512) + ch*32 + g;
#pragma unroll
                    for (int q = 0; q < 8; ++q) {
                        float4 v = arow[4*q];
                        acc[q].x += f*v.x; acc[q].y += f*v.y;
                        acc[q].z += f*v.z; acc[q].w += f*v.w;
                    }
                }
                __syncthreads();
#pragma unroll
                for (int q = 0; q < 8; ++q) {
                    int j4 = ch*32 + g + 4*q;
                    int c = j4 * 4;
                    float4 v = acc[q];
                    if (c >= c0 && c < c0 + 64) {
                        v.x = w_s[r*65 + (c-c0)];
                        v.y = w_s[r*65 + (c+1-c0)];
                        v.z = w_s[r*65 + (c+2-c0)];
                        v.w = w_s[r*65 + (c+3-c0)];
                    }
                    *(float4*)(stg + (size_t)(c0+r)*512 + c) = v;
                    *(float4*)(a_s + r*512 + c) = v;
                }
                __syncthreads();
            }
            __threadfence();
            if (tid == 0) flg[p] = 1;
            __syncthreads();
        } else {
            if (tid == 0) { while (flg[p] == 0) { } }
            __syncthreads();
            // ---- F = local panel block; zero panel cols ----
            for (int e = tid; e < 64*64; e += 256)
                w_s[(e>>6)*65 + (e&63)] = a_s[(e>>6)*512 + c0 + (e&63)];
            __syncthreads();
            for (int e = tid; e < 64*64; e += 256)
                a_s[(e>>6)*512 + c0 + (e&63)] = 0.f;
            __syncthreads();
            // ---- A -= F @ P, chunked over 128-col blocks ----
            for (int ch = 0; ch < 4; ++ch) {
                for (int e = tid; e < 64*32; e += 256) {
                    int row = e >> 5, j4 = e & 31;
                    float4 v = __ldcg((const float4*)(stg + (size_t)(c0+row)*512 + ch*128) + j4);
                    *(float4*)(p_s + row*132 + j4*4) = v;
                }
                __syncthreads();
                float4 acc[8];
#pragma unroll
                for (int q = 0; q < 8; ++q)
                    acc[q] = *((const float4*)(a_s + r*512) + ch*32 + g + 4*q);
                for (int k = 0; k < 64; ++k) {
                    float f = w_s[r*65+k];
                    const float4* prow = (const float4*)(p_s + k*132) + g;
#pragma unroll
                    for (int q = 0; q < 8; ++q) {
                        float4 v = prow[4*q];
                        acc[q].x -= f*v.x; acc[q].y -= f*v.y;
                        acc[q].z -= f*v.z; acc[q].w -= f*v.w;
                    }
                }
#pragma unroll
                for (int q = 0; q < 8; ++q)
                    *((float4*)(a_s + r*512) + ch*32 + g + 4*q) = acc[q];
                __syncthreads();
            }
        }
    }
    float* dst = prec + (size_t)b*NN*NN;
    for (int e = tid; e < 64*NN; e += 256)
        dst[(size_t)(r0 + (e>>9))*NN + (e & 511)] = a_s[e];
}

// ---------------- partial corr: tanh(-prec / sd sd), diag = tanh(1) -------
__global__ void k_pc(const float* __restrict__ prec, const float* __restrict__ sd,
                     float* __restrict__ out) {
    float t1 = tanhf(1.f);
    for (int e = blockIdx.x*blockDim.x + threadIdx.x; e < BB*NN*NN; e += gridDim.x*blockDim.x) {
        int b = e >> 18, r = e & 262143, i = r >> 9, j = r & 511;
        float v = (i == j) ? t1 : tanhf(-prec[e] / (sd[b*NN+i]*sd[b*NN+j]));
        out[e] = v;
    }
}

// ---------------- pairwise full-matrix dots (deterministic partials) ------
__global__ void k_dots(const float* __restrict__ P, const float* __restrict__ S,
                       const float* __restrict__ C, float* __restrict__ parts) {
    __shared__ float red[256];
    int b = blockIdx.y, ch = blockIdx.x;
    size_t base = (size_t)b*NN*NN + (size_t)ch*8192;
    float a[6] = {0,0,0,0,0,0};
    for (int e = threadIdx.x; e < 8192; e += 256) {
        float p = P[base+e], s = S[base+e], c = C[base+e];
        a[0] += p*p; a[1] += s*s; a[2] += c*c;
        a[3] += p*s; a[4] += p*c; a[5] += s*c;
    }
    for (int v = 0; v < 6; ++v) {
        red[threadIdx.x] = a[v]; __syncthreads();
        for (int o = 128; o > 0; o >>= 1) {
            if (threadIdx.x < o) red[threadIdx.x] += red[threadIdx.x + o];
            __syncthreads();
        }
        if (threadIdx.x == 0) parts[((size_t)b*32 + ch)*6 + v] = red[0];
        __syncthreads();
    }
}

// ---------------- sims + softmax alphas ----------------
__global__ void k_sims(const float* __restrict__ parts, const float* __restrict__ gamma,
                       float* __restrict__ alph) {
    int b = threadIdx.x;
    if (b >= BB) return;
    float F[6] = {0,0,0,0,0,0};
    for (int ch = 0; ch < 32; ++ch)
        for (int v = 0; v < 6; ++v) F[v] += parts[((size_t)b*32 + ch)*6 + v];
    float dC = tanhf(1.f);
    float dv[3] = {1.f, 1.f, dC};
    float D[3][3];
    D[0][0] = (F[0] - NN*dv[0]*dv[0]) * 0.5f;
    D[1][1] = (F[1] - NN*dv[1]*dv[1]) * 0.5f;
    D[2][2] = (F[2] - NN*dv[2]*dv[2]) * 0.5f;
    D[0][1] = D[1][0] = (F[3] - NN*dv[0]*dv[1]) * 0.5f;
    D[0][2] = D[2][0] = (F[4] - NN*dv[0]*dv[2]) * 0.5f;
    D[1][2] = D[2][1] = (F[5] - NN*dv[1]*dv[2]) * 0.5f;
    float rowsum[3], tot2 = 0.f;
    for (int v = 0; v < 3; ++v) {
        rowsum[v] = D[v][0] + D[v][1] + D[v][2];
        tot2 += rowsum[v];
    }
    float sims[3];
    for (int v = 0; v < 3; ++v) {
        float num = 0.5f * (rowsum[v] - D[v][v]);
        float nv = sqrtf(fmaxf(D[v][v], 0.f));
        float oo = 0.25f * (tot2 - 2.f*rowsum[v] + D[v][v]);
        float no = sqrtf(fmaxf(oo, 0.f));
        float den = fmaxf(nv, EPSF) * fmaxf(no, EPSF);
        sims[v] = num / den;
    }
    float g = gamma[0];
    float m = fmaxf(g*sims[0], fmaxf(g*sims[1], g*sims[2]));
    float e0 = expf(g*sims[0]-m), e1 = expf(g*sims[1]-m), e2 = expf(g*sims[2]-m);
    float si = 1.f / (e0 + e1 + e2);
    alph[b*4+0] = e0*si; alph[b*4+1] = e1*si; alph[b*4+2] = e2*si;
}

// ---------------- fuse + rowsum (C already symmetric to ~1e-7) ------------
__global__ __launch_bounds__(128) void k_fuse_rs(const float* __restrict__ P,
                      const float* __restrict__ S, const float* __restrict__ C,
                      const float* __restrict__ alph, float* __restrict__ Af,
                      float* __restrict__ dinv) {
    __shared__ float red[128];
    int bn = blockIdx.x;
    int b = bn >> 9, i = bn & 511;
    float aP = alph[b*4+0], aS = alph[b*4+1], aC = alph[b*4+2];
    size_t base = (size_t)bn*NN;
    float s = 0.f;
    for (int j = threadIdx.x; j < NN; j += 128) {
        float v = aP*P[base+j] + aS*S[base+j] + aC*C[base+j];
        if (j == i) v = 1.f;
        Af[base+j] = v;
        s += v;
    }
    red[threadIdx.x] = s; __syncthreads();
    for (int o = 64; o > 0; o >>= 1) {
        if (threadIdx.x < o) red[threadIdx.x] += red[threadIdx.x + o];
        __syncthreads();
    }
    if (threadIdx.x == 0) dinv[bn] = rsqrtf(fmaxf(red[0], EPSF));
}

__global__ void k_norm(const float* __restrict__ Af, const float* __restrict__ dinv,
                       float* __restrict__ An) {
    for (int e = blockIdx.x*blockDim.x + threadIdx.x; e < BB*NN*NN; e += gridDim.x*blockDim.x) {
        int b = e >> 18, r = e & 262143, i = r >> 9, j = r & 511;
        An[e] = dinv[b*NN+i] * Af[e] * dinv[b*NN+j];
    }
}

// ---------------- layernorm over concat(P,S,C) row ----------------
__global__ __launch_bounds__(256) void k_ln(const float* __restrict__ P, const float* __restrict__ S,
                     const float* __restrict__ C, const float* __restrict__ lng,
                     const float* __restrict__ lnb, float* __restrict__ X) {
    __shared__ float red[256];
    int bn = blockIdx.x;
    float v[6];
#pragma unroll
    for (int q = 0; q < 6; ++q) {
        int c = threadIdx.x + q*256;
        int view = c >> 9, off = c & 511;
        const float* M = (view == 0) ? P : (view == 1) ? S : C;
        v[q] = M[(size_t)bn*NN + off];
    }
    float s = v[0]+v[1]+v[2]+v[3]+v[4]+v[5];
    red[threadIdx.x] = s; __syncthreads();
    for (int o = 128; o > 0; o >>= 1) {
        if (threadIdx.x < o) red[threadIdx.x] += red[threadIdx.x + o];
        __syncthreads();
    }
    float mean = red[0] * (1.f/INDIM);
    __syncthreads();
    float ss = 0.f;
#pragma unroll
    for (int q = 0; q < 6; ++q) { float d = v[q]-mean; ss += d*d; }
    red[threadIdx.x] = ss; __syncthreads();
    for (int o = 128; o > 0; o >>= 1) {
        if (threadIdx.x < o) red[threadIdx.x] += red[threadIdx.x + o];
        __syncthreads();
    }
    float inv = rsqrtf(red[0]*(1.f/INDIM) + 1e-5f);
#pragma unroll
    for (int q = 0; q < 6; ++q) {
        int c = threadIdx.x + q*256;
        X[(size_t)bn*INDIM + c] = (v[q]-mean)*inv*lng[c] + lnb[c];
    }
}

// ---------------- batched SGEMM, double-buffered: C = act(A@B + bias) -----
__global__ __launch_bounds__(256,2) void k_mm(const float* __restrict__ A, long long sA,
                     const float* __restrict__ Bm, long long sB,
                     const float* __restrict__ bias,
                     float* __restrict__ Cm, long long sC, int K, int relu) {
    __shared__ float As[2][16][128];
    __shared__ float Bs[2][16][128];
    int bj = blockIdx.x, bi = blockIdx.y, b = blockIdx.z;
    int tid = threadIdx.x;
    int tx = tid & 15, ty = tid >> 4;
    const float* Ab = A + (size_t)b*sA;
    const float* Bb = Bm + (size_t)b*sB;

    int l0 = tid*2, l1 = tid*2 + 1;
    int rA0 = l0 >> 2, kA0 = (l0 & 3) * 4;
    int rA1 = l1 >> 2, kA1 = (l1 & 3) * 4;
    int kB0 = l0 >> 5, nB0 = (l0 & 31) * 4;
    int kB1 = l1 >> 5, nB1 = (l1 & 31) * 4;
    const float* A0 = Ab + (size_t)(bi*128+rA0)*K + kA0;
    const float* A1 = Ab + (size_t)(bi*128+rA1)*K + kA1;
    const float* B0 = Bb + (size_t)kB0*NN + bj*128 + nB0;
    const float* B1 = Bb + (size_t)kB1*NN + bj*128 + nB1;

    float acc[8][8];
#pragma unroll
    for (int i = 0; i < 8; ++i)
#pragma unroll
        for (int j = 0; j < 8; ++j) acc[i][j] = 0.f;

    float4 ra0 = *(const float4*)A0, ra1 = *(const float4*)A1;
    float4 rb0 = *(const float4*)B0, rb1 = *(const float4*)B1;
    As[0][kA0+0][rA0] = ra0.x; As[0][kA0+1][rA0] = ra0.y;
    As[0][kA0+2][rA0] = ra0.z; As[0][kA0+3][rA0] = ra0.w;
    As[0][kA1+0][rA1] = ra1.x; As[0][kA1+1][rA1] = ra1.y;
    As[0][kA1+2][rA1] = ra1.z; As[0][kA1+3][rA1] = ra1.w;
    *(float4*)&Bs[0][kB0][nB0] = rb0;
    *(float4*)&Bs[0][kB1][nB1] = rb1;
    __syncthreads();

    int buf = 0;
    for (int kt = 16; kt <= K; kt += 16) {
        bool more = (kt < K);
        if (more) {
            ra0 = *(const float4*)(A0 + kt); ra1 = *(const float4*)(A1 + kt);
            rb0 = *(const float4*)(B0 + (size_t)kt*NN);
            rb1 = *(const float4*)(B1 + (size_t)kt*NN);
        }
#pragma unroll
        for (int t = 0; t < 16; ++t) {
            float4 a0 = *(const float4*)&As[buf][t][ty*8];
            float4 a1 = *(const float4*)&As[buf][t][ty*8+4];
            float4 b0 = *(const float4*)&Bs[buf][t][tx*8];
            float4 b1 = *(const float4*)&Bs[buf][t][tx*8+4];
            float ar[8] = {a0.x,a0.y,a0.z,a0.w,a1.x,a1.y,a1.z,a1.w};
            float br[8] = {b0.x,b0.y,b0.z,b0.w,b1.x,b1.y,b1.z,b1.w};
#pragma unroll
            for (int i = 0; i < 8; ++i)
#pragma unroll
                for (int j = 0; j < 8; ++j) acc[i][j] += ar[i]*br[j];
        }
        if (more) {
            int nb = buf ^ 1;
            As[nb][kA0+0][rA0] = ra0.x; As[nb][kA0+1][rA0] = ra0.y;
            As[nb][kA0+2][rA0] = ra0.z; As[nb][kA0+3][rA0] = ra0.w;
            As[nb][kA1+0][rA1] = ra1.x; As[nb][kA1+1][rA1] = ra1.y;
            As[nb][kA1+2][rA1] = ra1.z; As[nb][kA1+3][rA1] = ra1.w;
            *(float4*)&Bs[nb][kB0][nB0] = rb0;
            *(float4*)&Bs[nb][kB1][nB1] = rb1;
            __syncthreads();
            buf = nb;
        }
    }
    float* Cb = Cm + (size_t)b*sC;
#pragma unroll
    for (int i = 0; i < 8; ++i) {
        int gi = bi*128 + ty*8 + i;
#pragma unroll
        for (int j = 0; j < 8; ++j) {
            int gj = bj*128 + tx*8 + j;
            float v = acc[i][j] + (bias ? bias[gj] : 0.f);
            if (relu) v = fmaxf(v, 0.f);
            Cb[(size_t)gi*NN + gj] = v;
        }
    }
}

// ---------------- head: mean over nodes, dot Wc, sigmoid ----------------
__global__ void k_head1(const float* __restrict__ H, float* __restrict__ part) {
    int b = blockIdx.y, ch = blockIdx.x, d = threadIdx.x;
    float s = 0.f;
#pragma unroll 8
    for (int r = 0; r < 32; ++r)
        s += H[((size_t)b*NN + ch*32 + r)*DD + d];
    part[((size_t)b*16 + ch)*DD + d] = s;
}

__global__ void k_head2(const float* __restrict__ part, const float* __restrict__ Wc,
                        const float* __restrict__ bc, float* __restrict__ out) {
    __shared__ float red[512];
    int b = blockIdx.x, d = threadIdx.x;
    float s = 0.f;
    for (int ch = 0; ch < 16; ++ch) s += part[((size_t)b*16 + ch)*DD + d];
    red[d] = (s * (1.f/NN)) * Wc[d];
    __syncthreads();
    for (int o = 256; o > 0; o >>= 1) {
        if (d < o) red[d] += red[d + o];
        __syncthreads();
    }
    if (d == 0) out[b] = 1.f / (1.f + expf(-(red[0] + bc[0])));
}

// ---------------- host ----------------
extern "C" void kernel_launch(void* const* d_in, const int* in_sizes, int n_in,
                              void* d_out, int out_size) {
    const float* x    = (const float*)d_in[0];
    const float* gam  = (const float*)d_in[1];
    const float* lng  = (const float*)d_in[2];
    const float* lnb  = (const float*)d_in[3];
    const float* W0   = (const float*)d_in[4];
    const float* b0   = (const float*)d_in[5];
    const float* W1   = (const float*)d_in[6];
    const float* b1   = (const float*)d_in[7];
    const float* W2   = (const float*)d_in[8];
    const float* b2   = (const float*)d_in[9];
    const float* Wc   = (const float*)d_in[10];
    const float* bc   = (const float*)d_in[11];
    float* out = (float*)d_out;

    float *pXt,*pRc,*pMu,*pCovP,*pCovS,*pP,*pS,*pPrec,*pC,*pAf,*pAn,*pX,*pY,*pH;
    float *pSdP,*pSdS,*pSdQ,*pParts,*pAl,*pDinv,*pStage;
    cudaGetSymbolAddress((void**)&pXt,   g_xt);
    cudaGetSymbolAddress((void**)&pRc,   g_rc);
    cudaGetSymbolAddress((void**)&pMu,   g_mu);
    cudaGetSymbolAddress((void**)&pCovP, g_covP);
    cudaGetSymbolAddress((void**)&pCovS, g_covS);
    cudaGetSymbolAddress((void**)&pP,    g_P);
    cudaGetSymbolAddress((void**)&pS,    g_S);
    cudaGetSymbolAddress((void**)&pPrec, g_prec);
    cudaGetSymbolAddress((void**)&pC,    g_C);
    cudaGetSymbolAddress((void**)&pAf,   g_Af);
    cudaGetSymbolAddress((void**)&pAn,   g_An);
    cudaGetSymbolAddress((void**)&pX,    g_X);
    cudaGetSymbolAddress((void**)&pY,    g_Ybuf);
    cudaGetSymbolAddress((void**)&pH,    g_Hbuf);
    cudaGetSymbolAddress((void**)&pSdP,  g_sdP);
    cudaGetSymbolAddress((void**)&pSdS,  g_sdS);
    cudaGetSymbolAddress((void**)&pSdQ,  g_sdQ);
    cudaGetSymbolAddress((void**)&pParts,g_parts);
    cudaGetSymbolAddress((void**)&pAl,   g_alph);
    cudaGetSymbolAddress((void**)&pDinv, g_dinv);
    cudaGetSymbolAddress((void**)&pStage,g_stage);

    const int INV_SMEM = (64*512 + 64*65 + 64*132) * 4;
    cudaFuncSetAttribute(k_inv, cudaFuncAttributeMaxDynamicSharedMemorySize, INV_SMEM);

    const float GSCALE = (float)(1.0 / (1023.0 + 1e-8));

    k_transpose<<<dim3(NN/32, TT/32, BB), dim3(32,8)>>>(x, pXt);
    k_mu<<<BB*NN, 256>>>(pXt, pMu);
    k_sort<<<BB*NN, 512>>>(pXt, pRc);

    k_gram<<<dim3(10, BB, 2), 256>>>(pXt, pRc, pMu, pCovP, pCovS, GSCALE);

    k_std<<<(BB*NN+255)/256, 256>>>(pCovP, pSdP);
    k_std<<<(BB*NN+255)/256, 256>>>(pCovS, pSdS);
    k_corr2<<<8192, 256>>>(pCovP, pSdP, pCovS, pSdS, pP, pS);

    k_zero<<<32, 256>>>();
    k_inv<<<128, 256, INV_SMEM>>>(pCovP, pPrec);
    k_std<<<(BB*NN+255)/256, 256>>>(pPrec, pSdQ);
    k_pc<<<8192, 256>>>(pPrec, pSdQ, pC);

    k_dots<<<dim3(32, BB), 256>>>(pP, pS, pC, pParts);
    k_sims<<<1, 32>>>(pParts, gam, pAl);
    k_fuse_rs<<<BB*NN, 128>>>(pP, pS, pC, pAl, pAf, pDinv);
    k_norm<<<8192, 256>>>(pAf, pDinv, pAn);
    k_ln<<<BB*NN, 256>>>(pP, pS, pC, lng, lnb, pX);

    long long sX = (long long)NN*INDIM, sM = (long long)NN*DD, sA2 = (long long)NN*NN;
    k_mm<<<dim3(4,4,BB), 256>>>(pX,  sX,  W0, 0LL, b0, pY, sM, INDIM, 0);
    k_mm<<<dim3(4,4,BB), 256>>>(pAn, sA2, pY, sM, (const float*)0, pH, sM, DD, 1);
    k_mm<<<dim3(4,4,BB), 256>>>(pH,  sM,  W1, 0LL, b1, pY, sM, DD, 0);
    k_mm<<<dim3(4,4,BB), 256>>>(pAn, sA2, pY, sM, (const float*)0, pH, sM, DD, 1);
    k_mm<<<dim3(4,4,BB), 256>>>(pH,  sM,  W2, 0LL, b2, pY, sM, DD, 0);
    k_mm<<<dim3(4,4,BB), 256>>>(pAn, sA2, pY, sM, (const float*)0, pH, sM, DD, 1);

    k_head1<<<dim3(16, BB), 512>>>(pH, pStage);
    k_head2<<<BB, 512>>>(pStage, Wc, bc, out);

    (void)in_sizes; (void)n_in; (void)out_size;
}

// round 8
// speedup vs baseline: 2.1304x; 1.4530x over previous
#include <cuda_runtime.h>
#include <math.h>

#define BB 16
#define TT 1024
#define NN 512
#define DD 512
#define INDIM 1536
#define EPSF 1e-8f

// ---------------- device scratch (no allocations allowed) ----------------
__device__ float g_xt  [BB*NN*TT];     // x transposed (B,N,T)
__device__ float g_rc  [BB*NN*TT];     // centered ranks (B,N,T)
__device__ float g_mu  [BB*NN];
__device__ float g_covP[BB*NN*NN];
__device__ float g_covS[BB*NN*NN];
__device__ float g_P   [BB*NN*NN];
__device__ float g_S   [BB*NN*NN];
__device__ float g_prec[BB*NN*NN];
__device__ float g_C   [BB*NN*NN];
__device__ float g_Af  [BB*NN*NN];
__device__ float g_An  [BB*NN*NN];
__device__ float g_X   [BB*NN*INDIM];
__device__ float g_Ybuf[BB*NN*DD];
__device__ float g_Hbuf[BB*NN*DD];
__device__ float g_stage[BB*NN*NN];    // GJ pivot-panel staging / head partials
__device__ int   g_flags[BB*NN];       // GJ panel flags
__device__ float g_sdP [BB*NN];
__device__ float g_sdS [BB*NN];
__device__ float g_sdQ [BB*NN];
__device__ float g_parts[BB*32*6];
__device__ float g_alph[BB*4];
__device__ float g_dinv[BB*NN];

__constant__ int c_BI[10] = {0,1,1,2,2,2,3,3,3,3};
__constant__ int c_BJ[10] = {0,0,1,0,1,2,0,1,2,3};

// ---------------- tf32 mma helpers ----------------
__device__ __forceinline__ unsigned su32(const void* p) {
    return (unsigned)__cvta_generic_to_shared(p);
}
__device__ __forceinline__ void cpa16(unsigned dst, const void* src) {
    asm volatile("cp.async.cg.shared.global [%0], [%1], 16;" :: "r"(dst), "l"(src));
}
__device__ __forceinline__ void cpcommit() { asm volatile("cp.async.commit_group;"); }
__device__ __forceinline__ void cpwait0()  { asm volatile("cp.async.wait_group 0;" ::: "memory"); }
__device__ __forceinline__ void mma_tf32(float* c,
        unsigned a0, unsigned a1, unsigned a2, unsigned a3,
        unsigned b0, unsigned b1) {
    asm volatile("mma.sync.aligned.m16n8k8.row.col.f32.tf32.tf32.f32 "
        "{%0,%1,%2,%3}, {%4,%5,%6,%7}, {%8,%9}, {%0,%1,%2,%3};"
        : "+f"(c[0]), "+f"(c[1]), "+f"(c[2]), "+f"(c[3])
        : "r"(a0), "r"(a1), "r"(a2), "r"(a3), "r"(b0), "r"(b1));
}

#define ASTR 36     // [row][k] stride (32 + 4 pad) -> conflict-free frags
#define BSTR 136    // [k][n]  stride (128 + 8 pad) -> conflict-free frags

// ---------------- transpose x (B,T,N) -> xt (B,N,T) ----------------
__global__ void k_transpose(const float* __restrict__ x, float* __restrict__ xt) {
    __shared__ float tile[32][33];
    int b = blockIdx.z;
    int n0 = blockIdx.x * 32, t0 = blockIdx.y * 32;
    for (int r = threadIdx.y; r < 32; r += 8)
        tile[r][threadIdx.x] = x[((size_t)b*TT + t0 + r)*NN + n0 + threadIdx.x];
    __syncthreads();
    for (int r = threadIdx.y; r < 32; r += 8)
        xt[((size_t)b*NN + n0 + r)*TT + t0 + threadIdx.x] = tile[threadIdx.x][r];
}

// ---------------- per-column means ----------------
__global__ void k_mu(const float* __restrict__ xt, float* __restrict__ mu) {
    __shared__ float red[256];
    int bn = blockIdx.x;
    const float* row = xt + (size_t)bn*TT;
    float s = 0.f;
    for (int t = threadIdx.x; t < TT; t += 256) s += row[t];
    red[threadIdx.x] = s; __syncthreads();
    for (int o = 128; o > 0; o >>= 1) {
        if (threadIdx.x < o) red[threadIdx.x] += red[threadIdx.x + o];
        __syncthreads();
    }
    if (threadIdx.x == 0) mu[bn] = red[0] * (1.f / TT);
}

// ---------------- bitonic argsort -> centered ranks ----------------
__global__ __launch_bounds__(512) void k_sort(const float* __restrict__ xt, float* __restrict__ rc) {
    __shared__ unsigned long long keys[1024];
    int bn = blockIdx.x;
    const float* row = xt + (size_t)bn*TT;
    for (int t = threadIdx.x; t < 1024; t += 512) {
        unsigned u = __float_as_uint(row[t]);
        u = (u & 0x80000000u) ? ~u : (u | 0x80000000u);
        keys[t] = ((unsigned long long)u << 32) | (unsigned)t;
    }
    __syncthreads();
    for (int k2 = 2; k2 <= 1024; k2 <<= 1)
        for (int j = k2 >> 1; j > 0; j >>= 1) {
            int t = threadIdx.x;
            int i = ((t & ~(j-1)) << 1) | (t & (j-1));
            int l = i | j;
            unsigned long long a = keys[i], b2 = keys[l];
            if ((a > b2) == ((i & k2) == 0)) { keys[i] = b2; keys[l] = a; }
            __syncthreads();
        }
    float* out = rc + (size_t)bn*TT;
    for (int p = threadIdx.x; p < 1024; p += 512) {
        int idx = (int)(keys[p] & 0xffffffffu);
        out[idx] = (float)(p+1) - 512.5f;
    }
}

// ---------------- tf32 Gram: C = X X^T, raw; Pearson fixed by rank-1 epi --
// z=0: Pearson (xt, mean-corrected in epilogue); z=1: Spearman (rc, exact).
__global__ __launch_bounds__(256) void k_gram_t(const float* __restrict__ xt,
        const float* __restrict__ rc, const float* __restrict__ mu,
        float* __restrict__ covP, float* __restrict__ covS, float scale) {
    extern __shared__ float sm[];
    float* AS = sm;                 // [2][128*ASTR]
    float* BS = sm + 2*128*ASTR;    // [2][128*ASTR]
    int p = blockIdx.x, b = blockIdx.y, z = blockIdx.z;
    int bi = c_BI[p], bj = c_BJ[p];
    int tid = threadIdx.x;
    int lane = tid & 31, w = tid >> 5;
    int gid = lane >> 2, tg = lane & 3;
    int wm = w & 1, wn = w >> 1;
    int m0w = wm*64, n0w = wn*32;
    const float* src = (z ? rc : xt) + (size_t)b*NN*TT;
    const float* Ab = src + (size_t)(bi*128)*TT;
    const float* Bb = src + (size_t)(bj*128)*TT;
    int ar = tid >> 1, ak = (tid & 1)*16;

    float c[4][4][4];
#pragma unroll
    for (int i = 0; i < 4; ++i)
#pragma unroll
        for (int j = 0; j < 4; ++j)
#pragma unroll
            for (int q = 0; q < 4; ++q) c[i][j][q] = 0.f;

    {
        const float* ga = Ab + (size_t)ar*TT + ak;
        unsigned da = su32(AS + ar*ASTR + ak);
        const float* gb = Bb + (size_t)ar*TT + ak;
        unsigned db = su32(BS + ar*ASTR + ak);
#pragma unroll
        for (int i = 0; i < 4; ++i) { cpa16(da + 16*i, ga + 4*i); cpa16(db + 16*i, gb + 4*i); }
        cpcommit();
    }
    int buf = 0;
    for (int kt = 0; kt < TT; kt += 32) {
        cpwait0(); __syncthreads();
        if (kt + 32 < TT) {
            int nb = buf ^ 1;
            const float* ga = Ab + (size_t)ar*TT + kt + 32 + ak;
            unsigned da = su32(AS + nb*128*ASTR + ar*ASTR + ak);
            const float* gb = Bb + (size_t)ar*TT + kt + 32 + ak;
            unsigned db = su32(BS + nb*128*ASTR + ar*ASTR + ak);
#pragma unroll
            for (int i = 0; i < 4; ++i) { cpa16(da + 16*i, ga + 4*i); cpa16(db + 16*i, gb + 4*i); }
            cpcommit();
        }
        const float* Asb = AS + buf*128*ASTR;
        const float* Bsb = BS + buf*128*ASTR;
#pragma unroll
        for (int ks = 0; ks < 4; ++ks) {
            int k0 = ks*8;
            unsigned af[4][4], bf[4][2];
#pragma unroll
            for (int mt = 0; mt < 4; ++mt) {
                int m = m0w + mt*16 + gid;
                af[mt][0] = __float_as_uint(Asb[(m  )*ASTR + k0 + tg]);
                af[mt][1] = __float_as_uint(Asb[(m+8)*ASTR + k0 + tg]);
                af[mt][2] = __float_as_uint(Asb[(m  )*ASTR + k0 + tg + 4]);
                af[mt][3] = __float_as_uint(Asb[(m+8)*ASTR + k0 + tg + 4]);
            }
#pragma unroll
            for (int nt = 0; nt < 4; ++nt) {
                int n = n0w + nt*8 + gid;
                bf[nt][0] = __float_as_uint(Bsb[n*ASTR + k0 + tg]);
                bf[nt][1] = __float_as_uint(Bsb[n*ASTR + k0 + tg + 4]);
            }
#pragma unroll
            for (int mt = 0; mt < 4; ++mt)
#pragma unroll
                for (int nt = 0; nt < 4; ++nt)
                    mma_tf32(c[mt][nt], af[mt][0], af[mt][1], af[mt][2], af[mt][3],
                             bf[nt][0], bf[nt][1]);
        }
        buf ^= 1;
    }
    float* Cb = (z ? covS : covP) + (size_t)b*NN*NN;
    const float* mub = mu + b*NN;
#pragma unroll
    for (int mt = 0; mt < 4; ++mt) {
#pragma unroll
        for (int nt = 0; nt < 4; ++nt) {
            int r0 = m0w + mt*16 + gid;
            int cb = n0w + nt*8 + tg*2;
            int gi0 = bi*128 + r0, gi1 = gi0 + 8;
            int gj0 = bj*128 + cb, gj1 = gj0 + 1;
            float v00 = c[mt][nt][0], v01 = c[mt][nt][1];
            float v10 = c[mt][nt][2], v11 = c[mt][nt][3];
            if (z == 0) {
                float mi0 = mub[gi0], mi1 = mub[gi1];
                float mj0 = mub[gj0], mj1 = mub[gj1];
                v00 -= 1024.f*mi0*mj0; v01 -= 1024.f*mi0*mj1;
                v10 -= 1024.f*mi1*mj0; v11 -= 1024.f*mi1*mj1;
            }
            v00 *= scale; v01 *= scale; v10 *= scale; v11 *= scale;
            *(float2*)&Cb[(size_t)gi0*NN + gj0] = make_float2(v00, v01);
            *(float2*)&Cb[(size_t)gi1*NN + gj0] = make_float2(v10, v11);
            if (bi != bj) {
                Cb[(size_t)gj0*NN + gi0] = v00;
                Cb[(size_t)gj1*NN + gi0] = v01;
                Cb[(size_t)gj0*NN + gi1] = v10;
                Cb[(size_t)gj1*NN + gi1] = v11;
            }
        }
    }
}

// ---------------- tf32 batched GEMM: C = act(A@B + bias), ldB=ldC=512 -----
__global__ __launch_bounds__(256) void k_mm_t(const float* __restrict__ A, long long sA,
        const float* __restrict__ Bm, long long sB, const float* __restrict__ bias,
        float* __restrict__ Cm, long long sC, int K, int relu) {
    extern __shared__ float sm[];
    float* AS = sm;                 // [2][128*ASTR]
    float* BS = sm + 2*128*ASTR;    // [2][32*BSTR]
    int bj = blockIdx.x, bi = blockIdx.y, b = blockIdx.z;
    int tid = threadIdx.x;
    int lane = tid & 31, w = tid >> 5;
    int gid = lane >> 2, tg = lane & 3;
    int wm = w & 1, wn = w >> 1;
    int m0w = wm*64, n0w = wn*32;
    const float* Ab = A + (size_t)b*sA + (size_t)(bi*128)*K;
    const float* Bb = Bm + (size_t)b*sB + bj*128;
    int ar = tid >> 1, ak = (tid & 1)*16;
    int bk = tid >> 3, bn = (tid & 7)*16;

    float c[4][4][4];
#pragma unroll
    for (int i = 0; i < 4; ++i)
#pragma unroll
        for (int j = 0; j < 4; ++j)
#pragma unroll
            for (int q = 0; q < 4; ++q) c[i][j][q] = 0.f;

    {
        const float* ga = Ab + (size_t)ar*K + ak;
        unsigned da = su32(AS + ar*ASTR + ak);
#pragma unroll
        for (int i = 0; i < 4; ++i) cpa16(da + 16*i, ga + 4*i);
        const float* gb = Bb + (size_t)bk*NN + bn;
        unsigned db = su32(BS + bk*BSTR + bn);
#pragma unroll
        for (int i = 0; i < 4; ++i) cpa16(db + 16*i, gb + 4*i);
        cpcommit();
    }
    int buf = 0;
    for (int kt = 0; kt < K; kt += 32) {
        cpwait0(); __syncthreads();
        if (kt + 32 < K) {
            int nb = buf ^ 1;
            const float* ga = Ab + (size_t)ar*K + kt + 32 + ak;
            unsigned da = su32(AS + nb*128*ASTR + ar*ASTR + ak);
#pragma unroll
            for (int i = 0; i < 4; ++i) cpa16(da + 16*i, ga + 4*i);
            const float* gb = Bb + (size_t)(kt + 32 + bk)*NN + bn;
            unsigned db = su32(BS + nb*32*BSTR + bk*BSTR + bn);
#pragma unroll
            for (int i = 0; i < 4; ++i) cpa16(db + 16*i, gb + 4*i);
            cpcommit();
        }
        const float* Asb = AS + buf*128*ASTR;
        const float* Bsb = BS + buf*32*BSTR;
#pragma unroll
        for (int ks = 0; ks < 4; ++ks) {
            int k0 = ks*8;
            unsigned af[4][4], bf[4][2];
#pragma unroll
            for (int mt = 0; mt < 4; ++mt) {
                int m = m0w + mt*16 + gid;
                af[mt][0] = __float_as_uint(Asb[(m  )*ASTR + k0 + tg]);
                af[mt][1] = __float_as_uint(Asb[(m+8)*ASTR + k0 + tg]);
                af[mt][2] = __float_as_uint(Asb[(m  )*ASTR + k0 + tg + 4]);
                af[mt][3] = __float_as_uint(Asb[(m+8)*ASTR + k0 + tg + 4]);
            }
#pragma unroll
            for (int nt = 0; nt < 4; ++nt) {
                int n = n0w + nt*8 + gid;
                bf[nt][0] = __float_as_uint(Bsb[(k0 + tg    )*BSTR + n]);
                bf[nt][1] = __float_as_uint(Bsb[(k0 + tg + 4)*BSTR + n]);
            }
#pragma unroll
            for (int mt = 0; mt < 4; ++mt)
#pragma unroll
                for (int nt = 0; nt < 4; ++nt)
                    mma_tf32(c[mt][nt], af[mt][0], af[mt][1], af[mt][2], af[mt][3],
                             bf[nt][0], bf[nt][1]);
        }
        buf ^= 1;
    }
    float* Cb = Cm + (size_t)b*sC + (size_t)(bi*128)*NN + bj*128;
#pragma unroll
    for (int mt = 0; mt < 4; ++mt) {
#pragma unroll
        for (int nt = 0; nt < 4; ++nt) {
            int r0 = m0w + mt*16 + gid;
            int cb = n0w + nt*8 + tg*2;
            float bz0 = bias ? bias[bj*128 + cb]     : 0.f;
            float bz1 = bias ? bias[bj*128 + cb + 1] : 0.f;
            float v00 = c[mt][nt][0] + bz0, v01 = c[mt][nt][1] + bz1;
            float v10 = c[mt][nt][2] + bz0, v11 = c[mt][nt][3] + bz1;
            if (relu) {
                v00 = fmaxf(v00, 0.f); v01 = fmaxf(v01, 0.f);
                v10 = fmaxf(v10, 0.f); v11 = fmaxf(v11, 0.f);
            }
            *(float2*)&Cb[(size_t)r0*NN + cb]     = make_float2(v00, v01);
            *(float2*)&Cb[(size_t)(r0+8)*NN + cb] = make_float2(v10, v11);
        }
    }
}

// ---------------- diag std ----------------
__global__ void k_std(const float* __restrict__ cov, float* __restrict__ sd) {
    int e = blockIdx.x*blockDim.x + threadIdx.x;
    if (e >= BB*NN) return;
    int b = e >> 9, n = e & 511;
    sd[e] = sqrtf(fmaxf(cov[((size_t)b*NN + n)*NN + n], EPSF));
}

// ---------------- corr (both P and S in one pass) ----------------
__global__ void k_corr2(const float* __restrict__ covP, const float* __restrict__ sdP,
                        const float* __restrict__ covS, const float* __restrict__ sdS,
                        float* __restrict__ P, float* __restrict__ S) {
    for (int e = blockIdx.x*blockDim.x + threadIdx.x; e < BB*NN*NN; e += gridDim.x*blockDim.x) {
        int b = e >> 18, r = e & 262143, i = r >> 9, j = r & 511;
        float vp, vs;
        if (i == j) { vp = 1.f; vs = 1.f; }
        else {
            vp = covP[e] / (sdP[b*NN+i]*sdP[b*NN+j]);
            if (!isfinite(vp)) vp = 0.f;
            vs = covS[e] / (sdS[b*NN+i]*sdS[b*NN+j]);
            if (!isfinite(vs)) vs = 0.f;
        }
        P[e] = vp; S[e] = vs;
    }
}

// ---------------- GJ flag reset ----------------
__global__ void k_zero() {
    int e = blockIdx.x*blockDim.x + threadIdx.x;
    if (e < BB*NN) g_flags[e] = 0;
}

// ---------------- blocked distributed Gauss-Jordan SPD inverse ------------
__global__ __launch_bounds__(256) void k_inv(const float* __restrict__ cov,
                                             float* __restrict__ prec) {
    extern __shared__ float smv[];
    float* a_s = smv;                          // 64*512
    float* w_s = smv + 64*512;                 // 64*65
    float* p_s = smv + 64*512 + 64*65;         // 64*132
    int cta = blockIdx.x;
    int b = cta >> 3, rb = cta & 7, r0 = rb * 64;
    int tid = threadIdx.x;
    int r = tid & 63, g = tid >> 6;
    const float* src = cov + (size_t)b*NN*NN;
    for (int e = tid; e < 64*NN; e += 256) {
        int i = e >> 9, j = e & 511;
        float v = src[(size_t)(r0+i)*NN + j];
        if (r0 + i == j) v += 0.001f;
        a_s[e] = v;
    }
    float* stg = g_stage + (size_t)b*NN*NN;
    volatile int* flg = g_flags + b*8;
    __syncthreads();

    for (int p = 0; p < 8; ++p) {
        int c0 = p * 64;
        if (rb == p) {
            for (int e = tid; e < 64*64; e += 256)
                w_s[(e>>6)*65 + (e&63)] = a_s[(e>>6)*512 + c0 + (e&63)];
            __syncthreads();
            for (int k = 0; k < 64; ++k) {
                float d = 1.0f / w_s[k*65+k];
                __syncthreads();
                if (tid < 64)
                    w_s[k*65+tid] = (tid == k) ? d : w_s[k*65+tid] * d;
                else if (tid < 128)
                    p_s[tid-64] = w_s[(tid-64)*65 + k];
                __syncthreads();
                for (int e = tid; e < 64*64; e += 256) {
                    int i = e >> 6, j = e & 63;
                    if (i == k) continue;
                    float f = p_s[i];
                    w_s[i*65+j] = (j == k) ? (-f*d) : (w_s[i*65+j] - f*w_s[k*65+j]);
                }
                __syncthreads();
            }
            for (int ch = 0; ch < 4; ++ch) {
                float4 acc[8];
#pragma unroll
                for (int q = 0; q < 8; ++q) acc[q] = make_float4(0.f,0.f,0.f,0.f);
                for (int k = 0; k < 64; ++k) {
                    float f = w_s[r*65+k];
                    const float4* arow = (const float4*)(a_s + k*512) + ch*32 + g;
#pragma unroll
                    for (int q = 0; q < 8; ++q) {
                        float4 v = arow[4*q];
                        acc[q].x += f*v.x; acc[q].y += f*v.y;
                        acc[q].z += f*v.z; acc[q].w += f*v.w;
                    }
                }
                __syncthreads();
#pragma unroll
                for (int q = 0; q < 8; ++q) {
                    int j4 = ch*32 + g + 4*q;
                    int c = j4 * 4;
                    float4 v = acc[q];
                    if (c >= c0 && c < c0 + 64) {
                        v.x = w_s[r*65 + (c-c0)];
                        v.y = w_s[r*65 + (c+1-c0)];
                        v.z = w_s[r*65 + (c+2-c0)];
                        v.w = w_s[r*65 + (c+3-c0)];
                    }
                    *(float4*)(stg + (size_t)(c0+r)*512 + c) = v;
                    *(float4*)(a_s + r*512 + c) = v;
                }
                __syncthreads();
            }
            __threadfence();
            if (tid == 0) flg[p] = 1;
            __syncthreads();
        } else {
            if (tid == 0) { while (flg[p] == 0) { } }
            __syncthreads();
            for (int e = tid; e < 64*64; e += 256)
                w_s[(e>>6)*65 + (e&63)] = a_s[(e>>6)*512 + c0 + (e&63)];
            __syncthreads();
            for (int e = tid; e < 64*64; e += 256)
                a_s[(e>>6)*512 + c0 + (e&63)] = 0.f;
            __syncthreads();
            for (int ch = 0; ch < 4; ++ch) {
                for (int e = tid; e < 64*32; e += 256) {
                    int row = e >> 5, j4 = e & 31;
                    float4 v = __ldcg((const float4*)(stg + (size_t)(c0+row)*512 + ch*128) + j4);
                    *(float4*)(p_s + row*132 + j4*4) = v;
                }
                __syncthreads();
                float4 acc[8];
#pragma unroll
                for (int q = 0; q < 8; ++q)
                    acc[q] = *((const float4*)(a_s + r*512) + ch*32 + g + 4*q);
                for (int k = 0; k < 64; ++k) {
                    float f = w_s[r*65+k];
                    const float4* prow = (const float4*)(p_s + k*132) + g;
#pragma unroll
                    for (int q = 0; q < 8; ++q) {
                        float4 v = prow[4*q];
                        acc[q].x -= f*v.x; acc[q].y -= f*v.y;
                        acc[q].z -= f*v.z; acc[q].w -= f*v.w;
                    }
                }
#pragma unroll
                for (int q = 0; q < 8; ++q)
                    *((float4*)(a_s + r*512) + ch*32 + g + 4*q) = acc[q];
                __syncthreads();
            }
        }
    }
    float* dst = prec + (size_t)b*NN*NN;
    for (int e = tid; e < 64*NN; e += 256)
        dst[(size_t)(r0 + (e>>9))*NN + (e & 511)] = a_s[e];
}

// ---------------- partial corr: tanh(-prec / sd sd), diag = tanh(1) -------
__global__ void k_pc(const float* __restrict__ prec, const float* __restrict__ sd,
                     float* __restrict__ out) {
    float t1 = tanhf(1.f);
    for (int e = blockIdx.x*blockDim.x + threadIdx.x; e < BB*NN*NN; e += gridDim.x*blockDim.x) {
        int b = e >> 18, r = e & 262143, i = r >> 9, j = r & 511;
        float v = (i == j) ? t1 : tanhf(-prec[e] / (sd[b*NN+i]*sd[b*NN+j]));
        out[e] = v;
    }
}

// ---------------- pairwise full-matrix dots (deterministic partials) ------
__global__ void k_dots(const float* __restrict__ P, const float* __restrict__ S,
                       const float* __restrict__ C, float* __restrict__ parts) {
    __shared__ float red[256];
    int b = blockIdx.y, ch = blockIdx.x;
    size_t base = (size_t)b*NN*NN + (size_t)ch*8192;
    float a[6] = {0,0,0,0,0,0};
    for (int e = threadIdx.x; e < 8192; e += 256) {
        float p = P[base+e], s = S[base+e], c = C[base+e];
        a[0] += p*p; a[1] += s*s; a[2] += c*c;
        a[3] += p*s; a[4] += p*c; a[5] += s*c;
    }
    for (int v = 0; v < 6; ++v) {
        red[threadIdx.x] = a[v]; __syncthreads();
        for (int o = 128; o > 0; o >>= 1) {
            if (threadIdx.x < o) red[threadIdx.x] += red[threadIdx.x + o];
            __syncthreads();
        }
        if (threadIdx.x == 0) parts[((size_t)b*32 + ch)*6 + v] = red[0];
        __syncthreads();
    }
}

// ---------------- sims + softmax alphas ----------------
__global__ void k_sims(const float* __restrict__ parts, const float* __restrict__ gamma,
                       float* __restrict__ alph) {
    int b = threadIdx.x;
    if (b >= BB) return;
    float F[6] = {0,0,0,0,0,0};
    for (int ch = 0; ch < 32; ++ch)
        for (int v = 0; v < 6; ++v) F[v] += parts[((size_t)b*32 + ch)*6 + v];
    float dC = tanhf(1.f);
    float dv[3] = {1.f, 1.f, dC};
    float D[3][3];
    D[0][0] = (F[0] - NN*dv[0]*dv[0]) * 0.5f;
    D[1][1] = (F[1] - NN*dv[1]*dv[1]) * 0.5f;
    D[2][2] = (F[2] - NN*dv[2]*dv[2]) * 0.5f;
    D[0][1] = D[1][0] = (F[3] - NN*dv[0]*dv[1]) * 0.5f;
    D[0][2] = D[2][0] = (F[4] - NN*dv[0]*dv[2]) * 0.5f;
    D[1][2] = D[2][1] = (F[5] - NN*dv[1]*dv[2]) * 0.5f;
    float rowsum[3], tot2 = 0.f;
    for (int v = 0; v < 3; ++v) {
        rowsum[v] = D[v][0] + D[v][1] + D[v][2];
        tot2 += rowsum[v];
    }
    float sims[3];
    for (int v = 0; v < 3; ++v) {
        float num = 0.5f * (rowsum[v] - D[v][v]);
        float nv = sqrtf(fmaxf(D[v][v], 0.f));
        float oo = 0.25f * (tot2 - 2.f*rowsum[v] + D[v][v]);
        float no = sqrtf(fmaxf(oo, 0.f));
        float den = fmaxf(nv, EPSF) * fmaxf(no, EPSF);
        sims[v] = num / den;
    }
    float g = gamma[0];
    float m = fmaxf(g*sims[0], fmaxf(g*sims[1], g*sims[2]));
    float e0 = expf(g*sims[0]-m), e1 = expf(g*sims[1]-m), e2 = expf(g*sims[2]-m);
    float si = 1.f / (e0 + e1 + e2);
    alph[b*4+0] = e0*si; alph[b*4+1] = e1*si; alph[b*4+2] = e2*si;
}

// ---------------- fuse + rowsum (C symmetric to ~1e-7) --------------------
__global__ __launch_bounds__(128) void k_fuse_rs(const float* __restrict__ P,
                      const float* __restrict__ S, const float* __restrict__ C,
                      const float* __restrict__ alph, float* __restrict__ Af,
                      float* __restrict__ dinv) {
    __shared__ float red[128];
    int bn = blockIdx.x;
    int b = bn >> 9, i = bn & 511;
    float aP = alph[b*4+0], aS = alph[b*4+1], aC = alph[b*4+2];
    size_t base = (size_t)bn*NN;
    float s = 0.f;
    for (int j = threadIdx.x; j < NN; j += 128) {
        float v = aP*P[base+j] + aS*S[base+j] + aC*C[base+j];
        if (j == i) v = 1.f;
        Af[base+j] = v;
        s += v;
    }
    red[threadIdx.x] = s; __syncthreads();
    for (int o = 64; o > 0; o >>= 1) {
        if (threadIdx.x < o) red[threadIdx.x] += red[threadIdx.x + o];
        __syncthreads();
    }
    if (threadIdx.x == 0) dinv[bn] = rsqrtf(fmaxf(red[0], EPSF));
}

__global__ void k_norm(const float* __restrict__ Af, const float* __restrict__ dinv,
                       float* __restrict__ An) {
    for (int e = blockIdx.x*blockDim.x + threadIdx.x; e < BB*NN*NN; e += gridDim.x*blockDim.x) {
        int b = e >> 18, r = e & 262143, i = r >> 9, j = r & 511;
        An[e] = dinv[b*NN+i] * Af[e] * dinv[b*NN+j];
    }
}

// ---------------- layernorm over concat(P,S,C) row ----------------
__global__ __launch_bounds__(256) void k_ln(const float* __restrict__ P, const float* __restrict__ S,
                     const float* __restrict__ C, const float* __restrict__ lng,
                     const float* __restrict__ lnb, float* __restrict__ X) {
    __shared__ float red[256];
    int bn = blockIdx.x;
    float v[6];
#pragma unroll
    for (int q = 0; q < 6; ++q) {
        int c = threadIdx.x + q*256;
        int view = c >> 9, off = c & 511;
        const float* M = (view == 0) ? P : (view == 1) ? S : C;
        v[q] = M[(size_t)bn*NN + off];
    }
    float s = v[0]+v[1]+v[2]+v[3]+v[4]+v[5];
    red[threadIdx.x] = s; __syncthreads();
    for (int o = 128; o > 0; o >>= 1) {
        if (threadIdx.x < o) red[threadIdx.x] += red[threadIdx.x + o];
        __syncthreads();
    }
    float mean = red[0] * (1.f/INDIM);
    __syncthreads();
    float ss = 0.f;
#pragma unroll
    for (int q = 0; q < 6; ++q) { float d = v[q]-mean; ss += d*d; }
    red[threadIdx.x] = ss; __syncthreads();
    for (int o = 128; o > 0; o >>= 1) {
        if (threadIdx.x < o) red[threadIdx.x] += red[threadIdx.x + o];
        __syncthreads();
    }
    float inv = rsqrtf(red[0]*(1.f/INDIM) + 1e-5f);
#pragma unroll
    for (int q = 0; q < 6; ++q) {
        int c = threadIdx.x + q*256;
        X[(size_t)bn*INDIM + c] = (v[q]-mean)*inv*lng[c] + lnb[c];
    }
}

// ---------------- head ----------------
__global__ void k_head1(const float* __restrict__ H, float* __restrict__ part) {
    int b = blockIdx.y, ch = blockIdx.x, d = threadIdx.x;
    float s = 0.f;
#pragma unroll 8
    for (int r = 0; r < 32; ++r)
        s += H[((size_t)b*NN + ch*32 + r)*DD + d];
    part[((size_t)b*16 + ch)*DD + d] = s;
}

__global__ void k_head2(const float* __restrict__ part, const float* __restrict__ Wc,
                        const float* __restrict__ bc, float* __restrict__ out) {
    __shared__ float red[512];
    int b = blockIdx.x, d = threadIdx.x;
    float s = 0.f;
    for (int ch = 0; ch < 16; ++ch) s += part[((size_t)b*16 + ch)*DD + d];
    red[d] = (s * (1.f/NN)) * Wc[d];
    __syncthreads();
    for (int o = 256; o > 0; o >>= 1) {
        if (d < o) red[d] += red[d + o];
        __syncthreads();
    }
    if (d == 0) out[b] = 1.f / (1.f + expf(-(red[0] + bc[0])));
}

// ---------------- host ----------------
extern "C" void kernel_launch(void* const* d_in, const int* in_sizes, int n_in,
                              void* d_out, int out_size) {
    const float* x    = (const float*)d_in[0];
    const float* gam  = (const float*)d_in[1];
    const float* lng  = (const float*)d_in[2];
    const float* lnb  = (const float*)d_in[3];
    const float* W0   = (const float*)d_in[4];
    const float* b0   = (const float*)d_in[5];
    const float* W1   = (const float*)d_in[6];
    const float* b1   = (const float*)d_in[7];
    const float* W2   = (const float*)d_in[8];
    const float* b2   = (const float*)d_in[9];
    const float* Wc   = (const float*)d_in[10];
    const float* bc   = (const float*)d_in[11];
    float* out = (float*)d_out;

    float *pXt,*pRc,*pMu,*pCovP,*pCovS,*pP,*pS,*pPrec,*pC,*pAf,*pAn,*pX,*pY,*pH;
    float *pSdP,*pSdS,*pSdQ,*pParts,*pAl,*pDinv,*pStage;
    cudaGetSymbolAddress((void**)&pXt,   g_xt);
    cudaGetSymbolAddress((void**)&pRc,   g_rc);
    cudaGetSymbolAddress((void**)&pMu,   g_mu);
    cudaGetSymbolAddress((void**)&pCovP, g_covP);
    cudaGetSymbolAddress((void**)&pCovS, g_covS);
    cudaGetSymbolAddress((void**)&pP,    g_P);
    cudaGetSymbolAddress((void**)&pS,    g_S);
    cudaGetSymbolAddress((void**)&pPrec, g_prec);
    cudaGetSymbolAddress((void**)&pC,    g_C);
    cudaGetSymbolAddress((void**)&pAf,   g_Af);
    cudaGetSymbolAddress((void**)&pAn,   g_An);
    cudaGetSymbolAddress((void**)&pX,    g_X);
    cudaGetSymbolAddress((void**)&pY,    g_Ybuf);
    cudaGetSymbolAddress((void**)&pH,    g_Hbuf);
    cudaGetSymbolAddress((void**)&pSdP,  g_sdP);
    cudaGetSymbolAddress((void**)&pSdS,  g_sdS);
    cudaGetSymbolAddress((void**)&pSdQ,  g_sdQ);
    cudaGetSymbolAddress((void**)&pParts,g_parts);
    cudaGetSymbolAddress((void**)&pAl,   g_alph);
    cudaGetSymbolAddress((void**)&pDinv, g_dinv);
    cudaGetSymbolAddress((void**)&pStage,g_stage);

    const int INV_SMEM  = (64*512 + 64*65 + 64*132) * 4;
    const int GRAM_SMEM = (4*128*ASTR) * 4;
    const int MM_SMEM   = (2*128*ASTR + 2*32*BSTR) * 4;
    cudaFuncSetAttribute(k_inv,    cudaFuncAttributeMaxDynamicSharedMemorySize, INV_SMEM);
    cudaFuncSetAttribute(k_gram_t, cudaFuncAttributeMaxDynamicSharedMemorySize, GRAM_SMEM);
    cudaFuncSetAttribute(k_mm_t,   cudaFuncAttributeMaxDynamicSharedMemorySize, MM_SMEM);

    const float GSCALE = (float)(1.0 / (1023.0 + 1e-8));

    k_transpose<<<dim3(NN/32, TT/32, BB), dim3(32,8)>>>(x, pXt);
    k_mu<<<BB*NN, 256>>>(pXt, pMu);
    k_sort<<<BB*NN, 512>>>(pXt, pRc);

    k_gram_t<<<dim3(10, BB, 2), 256, GRAM_SMEM>>>(pXt, pRc, pMu, pCovP, pCovS, GSCALE);

    k_std<<<(BB*NN+255)/256, 256>>>(pCovP, pSdP);
    k_std<<<(BB*NN+255)/256, 256>>>(pCovS, pSdS);
    k_corr2<<<8192, 256>>>(pCovP, pSdP, pCovS, pSdS, pP, pS);

    k_zero<<<32, 256>>>();
    k_inv<<<128, 256, INV_SMEM>>>(pCovP, pPrec);
    k_std<<<(BB*NN+255)/256, 256>>>(pPrec, pSdQ);
    k_pc<<<8192, 256>>>(pPrec, pSdQ, pC);

    k_dots<<<dim3(32, BB), 256>>>(pP, pS, pC, pParts);
    k_sims<<<1, 32>>>(pParts, gam, pAl);
    k_fuse_rs<<<BB*NN, 128>>>(pP, pS, pC, pAl, pAf, pDinv);
    k_norm<<<8192, 256>>>(pAf, pDinv, pAn);
    k_ln<<<BB*NN, 256>>>(pP, pS, pC, lng, lnb, pX);

    long long sX = (long long)NN*INDIM, sM = (long long)NN*DD, sA2 = (long long)NN*NN;
    k_mm_t<<<dim3(4,4,BB), 256, MM_SMEM>>>(pX,  sX,  W0, 0LL, b0, pY, sM, INDIM, 0);
    k_mm_t<<<dim3(4,4,BB), 256, MM_SMEM>>>(pAn, sA2, pY, sM, (const float*)0, pH, sM, DD, 1);
    k_mm_t<<<dim3(4,4,BB), 256, MM_SMEM>>>(pH,  sM,  W1, 0LL, b1, pY, sM, DD, 0);
    k_mm_t<<<dim3(4,4,BB), 256, MM_SMEM>>>(pAn, sA2, pY, sM, (const float*)0, pH, sM, DD, 1);
    k_mm_t<<<dim3(4,4,BB), 256, MM_SMEM>>>(pH,  sM,  W2, 0LL, b2, pY, sM, DD, 0);
    k_mm_t<<<dim3(4,4,BB), 256, MM_SMEM>>>(pAn, sA2, pY, sM, (const float*)0, pH, sM, DD, 1);

    k_head1<<<dim3(16, BB), 512>>>(pH, pStage);
    k_head2<<<BB, 512>>>(pStage, Wc, bc, out);

    (void)in_sizes; (void)n_in; (void)out_size;
}